// round 1
// baseline (speedup 1.0000x reference)
#include <cuda_runtime.h>
#include <cuda_bf16.h>

// ---------------------------------------------------------------------------
// GraphSAGE 2-layer, N=50000, E=800000, D=128.
//
// Restructure: (segment_sum(x[src]) / deg) @ W  ==  segment_sum((x@W)[src]) / deg
// so per layer:
//   Y = x @ Wl            (tiled fp32 SGEMM)
//   Z = x @ Wr            (tiled fp32 SGEMM)
//   ACC = scatter-add Y[src] -> dst      (atomics; features L2-resident)
//   out = [relu](ACC/max(deg,1) + Z + b)
// deg computed once per call.
// ---------------------------------------------------------------------------

#define NMAX 50000
#define D 128

__device__ float g_Y[NMAX * D];
__device__ float g_Z[NMAX * D];
__device__ float g_ACC[NMAX * D];
__device__ float g_H[NMAX * D];
__device__ float g_DEG[NMAX];
__device__ int   g_is64;

// ---------------------------------------------------------------------------
// Detect whether edge_index is int64 or int32 (JAX may silently downcast).
// If int64 little-endian, odd 32-bit words are high halves == 0 (ids < 2^31).
// If int32, odd words are random node ids in [0, 50000): all-zero impossible.
// ---------------------------------------------------------------------------
__global__ void detect_kernel(const unsigned int* __restrict__ ei) {
    if (threadIdx.x == 0 && blockIdx.x == 0) {
        int all_zero = 1;
        for (int i = 0; i < 128; i++) {
            if (ei[2 * i + 1] != 0u) { all_zero = 0; break; }
        }
        g_is64 = all_zero;
    }
}

// ---------------------------------------------------------------------------
// Zero helpers (reference device globals directly; no symbol plumbing needed)
// ---------------------------------------------------------------------------
__global__ void zero_acc_kernel(int n4) {
    int i = blockIdx.x * blockDim.x + threadIdx.x;
    if (i < n4) reinterpret_cast<float4*>(g_ACC)[i] = make_float4(0.f, 0.f, 0.f, 0.f);
}
__global__ void zero_deg_kernel(int n4) {
    int i = blockIdx.x * blockDim.x + threadIdx.x;
    if (i < n4) reinterpret_cast<float4*>(g_DEG)[i] = make_float4(0.f, 0.f, 0.f, 0.f);
}

// ---------------------------------------------------------------------------
// Degree: one thread per edge, float atomic counter on dst.
// ---------------------------------------------------------------------------
__global__ void deg_kernel(const void* __restrict__ ei, int E) {
    int e = blockIdx.x * blockDim.x + threadIdx.x;
    if (e >= E) return;
    long long dst;
    if (g_is64) dst = reinterpret_cast<const long long*>(ei)[E + e];
    else        dst = (long long)reinterpret_cast<const int*>(ei)[E + e];
    atomicAdd(&g_DEG[dst], 1.0f);
}

// ---------------------------------------------------------------------------
// Tiled fp32 SGEMM: C[N,128] = A[N,128] @ W[128,128]
// BM=128, BN=128, BK=16, 256 threads, 8x8 per-thread tile.
// ---------------------------------------------------------------------------
__global__ __launch_bounds__(256) void sgemm128(const float* __restrict__ A,
                                                const float* __restrict__ W,
                                                float* __restrict__ C, int N) {
    __shared__ float As[16][132];  // padded, stored transposed: As[k][row]
    __shared__ float Bs[16][128];

    const int tid  = threadIdx.x;
    const int row0 = blockIdx.x * 128;
    const int ty   = tid >> 4;   // 0..15
    const int tx   = tid & 15;   // 0..15

    float acc[8][8];
#pragma unroll
    for (int i = 0; i < 8; i++)
#pragma unroll
        for (int j = 0; j < 8; j++) acc[i][j] = 0.f;

    for (int kb = 0; kb < 128; kb += 16) {
        // load A tile (128 rows x 16 k) transposed into As
#pragma unroll
        for (int l = 0; l < 2; l++) {
            int f  = tid + l * 256;      // 0..511 float4 slots
            int r  = f >> 2;             // 0..127 row-in-tile
            int kc = (f & 3) * 4;        // 0,4,8,12
            float4 v = make_float4(0.f, 0.f, 0.f, 0.f);
            int grow = row0 + r;
            if (grow < N)
                v = *reinterpret_cast<const float4*>(A + (long long)grow * 128 + kb + kc);
            As[kc + 0][r] = v.x; As[kc + 1][r] = v.y;
            As[kc + 2][r] = v.z; As[kc + 3][r] = v.w;
        }
        // load W tile (16 k x 128 cols)
#pragma unroll
        for (int l = 0; l < 2; l++) {
            int f = tid + l * 256;
            int r = f >> 5;              // 0..15
            int c = (f & 31) * 4;        // 0..124
            *reinterpret_cast<float4*>(&Bs[r][c]) =
                *reinterpret_cast<const float4*>(W + (kb + r) * 128 + c);
        }
        __syncthreads();

#pragma unroll
        for (int kk = 0; kk < 16; kk++) {
            float a[8], b[8];
#pragma unroll
            for (int i = 0; i < 8; i++) a[i] = As[kk][ty * 8 + i];
#pragma unroll
            for (int j = 0; j < 8; j++) b[j] = Bs[kk][tx * 8 + j];
#pragma unroll
            for (int i = 0; i < 8; i++)
#pragma unroll
                for (int j = 0; j < 8; j++) acc[i][j] += a[i] * b[j];
        }
        __syncthreads();
    }

#pragma unroll
    for (int i = 0; i < 8; i++) {
        int grow = row0 + ty * 8 + i;
        if (grow < N) {
#pragma unroll
            for (int j = 0; j < 8; j += 4) {
                float4 v = make_float4(acc[i][j], acc[i][j + 1], acc[i][j + 2], acc[i][j + 3]);
                *reinterpret_cast<float4*>(C + (long long)grow * 128 + tx * 8 + j) = v;
            }
        }
    }
}

// ---------------------------------------------------------------------------
// Scatter-add: one warp per edge. Each lane moves one float4 (4 atomics).
// Y and feature matrix are L2-resident (25.6 MB each).
// ---------------------------------------------------------------------------
__global__ __launch_bounds__(256) void scatter_kernel(const void* __restrict__ ei, int E) {
    int w    = (blockIdx.x * blockDim.x + threadIdx.x) >> 5;
    int lane = threadIdx.x & 31;
    if (w >= E) return;
    long long src, dst;
    if (g_is64) {
        const long long* p = reinterpret_cast<const long long*>(ei);
        src = p[w]; dst = p[E + w];
    } else {
        const int* p = reinterpret_cast<const int*>(ei);
        src = p[w]; dst = p[E + w];
    }
    float4 v = *reinterpret_cast<const float4*>(g_Y + src * 128 + lane * 4);
    float* o = g_ACC + dst * 128 + lane * 4;
    atomicAdd(o + 0, v.x);
    atomicAdd(o + 1, v.y);
    atomicAdd(o + 2, v.z);
    atomicAdd(o + 3, v.w);
}

// ---------------------------------------------------------------------------
// Finalize: out = [relu](ACC/max(deg,1) + Z + bias). float4 per thread.
// ---------------------------------------------------------------------------
__global__ void finalize_kernel(const float* __restrict__ Zp,
                                const float* __restrict__ bias,
                                float* __restrict__ out, int N, int do_relu) {
    int i = blockIdx.x * blockDim.x + threadIdx.x;   // over N*32 float4s
    if (i >= N * 32) return;
    int row = i >> 5;
    int c4  = (i & 31) * 4;
    float d = g_DEG[row];
    if (d < 1.f) d = 1.f;
    float inv = 1.f / d;
    float4 a = *reinterpret_cast<const float4*>(g_ACC + (long long)row * 128 + c4);
    float4 z = *reinterpret_cast<const float4*>(Zp + (long long)row * 128 + c4);
    float4 b = *reinterpret_cast<const float4*>(bias + c4);
    float4 r;
    r.x = fmaf(a.x, inv, z.x + b.x);
    r.y = fmaf(a.y, inv, z.y + b.y);
    r.z = fmaf(a.z, inv, z.z + b.z);
    r.w = fmaf(a.w, inv, z.w + b.w);
    if (do_relu) {
        r.x = fmaxf(r.x, 0.f); r.y = fmaxf(r.y, 0.f);
        r.z = fmaxf(r.z, 0.f); r.w = fmaxf(r.w, 0.f);
    }
    *reinterpret_cast<float4*>(out + (long long)row * 128 + c4) = r;
}

// ---------------------------------------------------------------------------
// Host launcher (graph-capturable: kernel launches only)
// ---------------------------------------------------------------------------
extern "C" void kernel_launch(void* const* d_in, const int* in_sizes, int n_in,
                              void* d_out, int out_size) {
    const float* x   = (const float*)d_in[0];
    const void*  ei  = d_in[1];
    const float* W1l = (const float*)d_in[2];
    const float* b1l = (const float*)d_in[3];
    const float* W1r = (const float*)d_in[4];
    const float* W2l = (const float*)d_in[5];
    const float* b2l = (const float*)d_in[6];
    const float* W2r = (const float*)d_in[7];
    float* out = (float*)d_out;

    const int N = in_sizes[0] / D;        // 50000
    const int E = in_sizes[1] / 2;        // 800000

    void *pY, *pZ, *pH;
    cudaGetSymbolAddress(&pY, g_Y);
    cudaGetSymbolAddress(&pZ, g_Z);
    cudaGetSymbolAddress(&pH, g_H);
    float* Y = (float*)pY;
    float* Z = (float*)pZ;
    float* H = (float*)pH;

    const int gemm_blocks  = (N + 127) / 128;
    const int acc4         = N * 32;                 // float4 count of ACC
    const int deg4         = N / 4;
    const int scat_blocks  = (E + 7) / 8;            // 8 warps/block, warp/edge
    const int fin_blocks   = (N * 32 + 255) / 256;

    detect_kernel<<<1, 32>>>((const unsigned int*)ei);

    // degree (once)
    zero_deg_kernel<<<(deg4 + 255) / 256, 256>>>(deg4);
    deg_kernel<<<(E + 255) / 256, 256>>>(ei, E);

    // ---------------- layer 1 ----------------
    zero_acc_kernel<<<(acc4 + 255) / 256, 256>>>(acc4);
    sgemm128<<<gemm_blocks, 256>>>(x, W1l, Y, N);
    sgemm128<<<gemm_blocks, 256>>>(x, W1r, Z, N);
    scatter_kernel<<<scat_blocks, 256>>>(ei, E);
    finalize_kernel<<<fin_blocks, 256>>>(Z, b1l, H, N, /*relu=*/1);

    // ---------------- layer 2 ----------------
    zero_acc_kernel<<<(acc4 + 255) / 256, 256>>>(acc4);
    sgemm128<<<gemm_blocks, 256>>>(H, W2l, Y, N);
    sgemm128<<<gemm_blocks, 256>>>(H, W2r, Z, N);
    scatter_kernel<<<scat_blocks, 256>>>(ei, E);
    finalize_kernel<<<fin_blocks, 256>>>(Z, b2l, out, N, /*relu=*/0);
}

// round 2
// speedup vs baseline: 1.6146x; 1.6146x over previous
#include <cuda_runtime.h>
#include <cuda_bf16.h>

// ---------------------------------------------------------------------------
// GraphSAGE 2-layer, N=50000, E=800000, D=128.
//
// Restructure: (segment_sum(x[src]) / deg) @ W  ==  segment_sum((x@W)[src]) / deg
// Per layer:
//   Y = x @ Wl, Z = x @ Wr       (tiled fp32 SGEMM)
//   ACC = scatter-add Y[src]->dst  via red.global.add.v4.f32 (L2-resident)
//   out = [relu](ACC/max(deg,1) + Z + b)
// ---------------------------------------------------------------------------

#define NMAX 50000
#define D 128

__device__ float g_Y[NMAX * D];
__device__ float g_Z[NMAX * D];
__device__ float g_ACC[NMAX * D];
__device__ float g_H[NMAX * D];
__device__ float g_DEG[NMAX];
__device__ int   g_is64;

// ---------------------------------------------------------------------------
// Detect int64 vs int32 edge_index (JAX may silently downcast).
// ---------------------------------------------------------------------------
__global__ void detect_kernel(const unsigned int* __restrict__ ei) {
    if (threadIdx.x == 0 && blockIdx.x == 0) {
        int all_zero = 1;
        for (int i = 0; i < 128; i++) {
            if (ei[2 * i + 1] != 0u) { all_zero = 0; break; }
        }
        g_is64 = all_zero;
    }
}

// ---------------------------------------------------------------------------
// Zero ACC (N*128 floats) and DEG (N floats) in one kernel.
// ---------------------------------------------------------------------------
__global__ void zero_acc_deg_kernel(int acc4, int deg4, int do_deg) {
    int i = blockIdx.x * blockDim.x + threadIdx.x;
    float4 z = make_float4(0.f, 0.f, 0.f, 0.f);
    if (i < acc4) reinterpret_cast<float4*>(g_ACC)[i] = z;
    if (do_deg && i < deg4) reinterpret_cast<float4*>(g_DEG)[i] = z;
}

// ---------------------------------------------------------------------------
// Degree: one thread per edge.
// ---------------------------------------------------------------------------
__global__ void deg_kernel(const void* __restrict__ ei, int E) {
    int e = blockIdx.x * blockDim.x + threadIdx.x;
    if (e >= E) return;
    long long dst;
    if (g_is64) dst = reinterpret_cast<const long long*>(ei)[E + e];
    else        dst = (long long)reinterpret_cast<const int*>(ei)[E + e];
    atomicAdd(&g_DEG[dst], 1.0f);
}

// ---------------------------------------------------------------------------
// Tiled fp32 SGEMM: C[N,128] = A[N,128] @ W[128,128]
// BM=128, BN=128, BK=16, 256 threads, 8x8 per-thread tile.
// ---------------------------------------------------------------------------
__global__ __launch_bounds__(256) void sgemm128(const float* __restrict__ A,
                                                const float* __restrict__ W,
                                                float* __restrict__ C, int N) {
    __shared__ float As[16][132];  // padded, transposed: As[k][row]
    __shared__ float Bs[16][128];

    const int tid  = threadIdx.x;
    const int row0 = blockIdx.x * 128;
    const int ty   = tid >> 4;   // 0..15
    const int tx   = tid & 15;   // 0..15

    float acc[8][8];
#pragma unroll
    for (int i = 0; i < 8; i++)
#pragma unroll
        for (int j = 0; j < 8; j++) acc[i][j] = 0.f;

    for (int kb = 0; kb < 128; kb += 16) {
#pragma unroll
        for (int l = 0; l < 2; l++) {
            int f  = tid + l * 256;
            int r  = f >> 2;
            int kc = (f & 3) * 4;
            float4 v = make_float4(0.f, 0.f, 0.f, 0.f);
            int grow = row0 + r;
            if (grow < N)
                v = *reinterpret_cast<const float4*>(A + (long long)grow * 128 + kb + kc);
            As[kc + 0][r] = v.x; As[kc + 1][r] = v.y;
            As[kc + 2][r] = v.z; As[kc + 3][r] = v.w;
        }
#pragma unroll
        for (int l = 0; l < 2; l++) {
            int f = tid + l * 256;
            int r = f >> 5;
            int c = (f & 31) * 4;
            *reinterpret_cast<float4*>(&Bs[r][c]) =
                *reinterpret_cast<const float4*>(W + (kb + r) * 128 + c);
        }
        __syncthreads();

#pragma unroll
        for (int kk = 0; kk < 16; kk++) {
            float a[8], b[8];
#pragma unroll
            for (int i = 0; i < 8; i++) a[i] = As[kk][ty * 8 + i];
#pragma unroll
            for (int j = 0; j < 8; j++) b[j] = Bs[kk][tx * 8 + j];
#pragma unroll
            for (int i = 0; i < 8; i++)
#pragma unroll
                for (int j = 0; j < 8; j++) acc[i][j] += a[i] * b[j];
        }
        __syncthreads();
    }

#pragma unroll
    for (int i = 0; i < 8; i++) {
        int grow = row0 + ty * 8 + i;
        if (grow < N) {
#pragma unroll
            for (int j = 0; j < 8; j += 4) {
                float4 v = make_float4(acc[i][j], acc[i][j + 1], acc[i][j + 2], acc[i][j + 3]);
                *reinterpret_cast<float4*>(C + (long long)grow * 128 + tx * 8 + j) = v;
            }
        }
    }
}

// ---------------------------------------------------------------------------
// Scatter-add: one warp per edge; each lane one float4 gather + one
// red.global.add.v4.f32 (16B vector reduction -> 4x fewer L2 atomic ops).
// ---------------------------------------------------------------------------
__global__ __launch_bounds__(256) void scatter_kernel(const void* __restrict__ ei, int E) {
    int w    = (blockIdx.x * blockDim.x + threadIdx.x) >> 5;
    int lane = threadIdx.x & 31;
    if (w >= E) return;
    long long src, dst;
    if (g_is64) {
        const long long* p = reinterpret_cast<const long long*>(ei);
        src = p[w]; dst = p[E + w];
    } else {
        const int* p = reinterpret_cast<const int*>(ei);
        src = p[w]; dst = p[E + w];
    }
    float4 v = *reinterpret_cast<const float4*>(g_Y + src * 128 + lane * 4);
    float* o = g_ACC + dst * 128 + lane * 4;
    asm volatile("red.global.add.v4.f32 [%0], {%1, %2, %3, %4};"
                 :: "l"(o), "f"(v.x), "f"(v.y), "f"(v.z), "f"(v.w)
                 : "memory");
}

// ---------------------------------------------------------------------------
// Finalize: out = [relu](ACC/max(deg,1) + Z + bias).
// ---------------------------------------------------------------------------
__global__ void finalize_kernel(const float* __restrict__ Zp,
                                const float* __restrict__ bias,
                                float* __restrict__ out, int N, int do_relu) {
    int i = blockIdx.x * blockDim.x + threadIdx.x;
    if (i >= N * 32) return;
    int row = i >> 5;
    int c4  = (i & 31) * 4;
    float d = g_DEG[row];
    if (d < 1.f) d = 1.f;
    float inv = 1.f / d;
    float4 a = *reinterpret_cast<const float4*>(g_ACC + (long long)row * 128 + c4);
    float4 z = *reinterpret_cast<const float4*>(Zp + (long long)row * 128 + c4);
    float4 b = *reinterpret_cast<const float4*>(bias + c4);
    float4 r;
    r.x = fmaf(a.x, inv, z.x + b.x);
    r.y = fmaf(a.y, inv, z.y + b.y);
    r.z = fmaf(a.z, inv, z.z + b.z);
    r.w = fmaf(a.w, inv, z.w + b.w);
    if (do_relu) {
        r.x = fmaxf(r.x, 0.f); r.y = fmaxf(r.y, 0.f);
        r.z = fmaxf(r.z, 0.f); r.w = fmaxf(r.w, 0.f);
    }
    *reinterpret_cast<float4*>(out + (long long)row * 128 + c4) = r;
}

// ---------------------------------------------------------------------------
// Host launcher (graph-capturable: kernel launches only)
// ---------------------------------------------------------------------------
extern "C" void kernel_launch(void* const* d_in, const int* in_sizes, int n_in,
                              void* d_out, int out_size) {
    const float* x   = (const float*)d_in[0];
    const void*  ei  = d_in[1];
    const float* W1l = (const float*)d_in[2];
    const float* b1l = (const float*)d_in[3];
    const float* W1r = (const float*)d_in[4];
    const float* W2l = (const float*)d_in[5];
    const float* b2l = (const float*)d_in[6];
    const float* W2r = (const float*)d_in[7];
    float* out = (float*)d_out;

    const int N = in_sizes[0] / D;        // 50000
    const int E = in_sizes[1] / 2;        // 800000

    void *pY, *pZ, *pH;
    cudaGetSymbolAddress(&pY, g_Y);
    cudaGetSymbolAddress(&pZ, g_Z);
    cudaGetSymbolAddress(&pH, g_H);
    float* Y = (float*)pY;
    float* Z = (float*)pZ;
    float* H = (float*)pH;

    const int gemm_blocks  = (N + 127) / 128;
    const int acc4         = N * 32;
    const int deg4         = N / 4;
    const int zero_blocks  = (acc4 + 255) / 256;
    const int scat_blocks  = (E + 7) / 8;
    const int fin_blocks   = (N * 32 + 255) / 256;

    detect_kernel<<<1, 32>>>((const unsigned int*)ei);

    // ---------------- layer 1 (+deg once) ----------------
    zero_acc_deg_kernel<<<zero_blocks, 256>>>(acc4, deg4, 1);
    deg_kernel<<<(E + 255) / 256, 256>>>(ei, E);
    sgemm128<<<gemm_blocks, 256>>>(x, W1l, Y, N);
    sgemm128<<<gemm_blocks, 256>>>(x, W1r, Z, N);
    scatter_kernel<<<scat_blocks, 256>>>(ei, E);
    finalize_kernel<<<fin_blocks, 256>>>(Z, b1l, H, N, /*relu=*/1);

    // ---------------- layer 2 ----------------
    zero_acc_deg_kernel<<<zero_blocks, 256>>>(acc4, deg4, 0);
    sgemm128<<<gemm_blocks, 256>>>(H, W2l, Y, N);
    sgemm128<<<gemm_blocks, 256>>>(H, W2r, Z, N);
    scatter_kernel<<<scat_blocks, 256>>>(ei, E);
    finalize_kernel<<<fin_blocks, 256>>>(Z, b2l, out, N, /*relu=*/0);
}